// round 1
// baseline (speedup 1.0000x reference)
#include <cuda_runtime.h>
#include <math.h>

#define N0 2048
#define NPAD 4096
#define NTHREADS 256

#define EPS 0.05f
// log2(e)/EPS
#define KCONST 28.853900817779268f
// EPS * (-log(4096))
#define ACONST -0.41588830833596715f
#define SCALE 4096.0f

// ---- device state (no allocations allowed; static globals) ----
__device__ float g_u[N0];
__device__ float g_v[N0];
__device__ float g_upad;
__device__ float g_vpad;
__device__ float g_w[N0];      // (x_j - x_max)*KCONST for the "other" potential
__device__ float g_P;          // 2048 * exp((x_pad - x_max)/eps)
__device__ float g_base;       // ACONST - x_max
__device__ unsigned int g_counter = 0;
__device__ float g_CT[(size_t)N0 * N0];   // C transposed (16 MB scratch)

__device__ __forceinline__ float ex2(float x) {
    float y;
    asm("ex2.approx.ftz.f32 %0, %1;" : "=f"(y) : "f"(x));
    return y;
}

__device__ __forceinline__ float warpRedSum(float v) {
#pragma unroll
    for (int o = 16; o > 0; o >>= 1) v += __shfl_down_sync(0xffffffffu, v, o);
    return v;
}
__device__ __forceinline__ float warpRedMax(float v) {
#pragma unroll
    for (int o = 16; o > 0; o >>= 1) v = fmaxf(v, __shfl_down_sync(0xffffffffu, v, o));
    return v;
}

// result valid in thread 0
__device__ float blockSum(float v) {
    __shared__ float sh[NTHREADS / 32];
    __syncthreads();   // safe reuse across calls
    int lane = threadIdx.x & 31, w = threadIdx.x >> 5;
    v = warpRedSum(v);
    if (lane == 0) sh[w] = v;
    __syncthreads();
    if (w == 0) {
        v = (lane < NTHREADS / 32) ? sh[lane] : 0.0f;
        v = warpRedSum(v);
    }
    return v;
}
// result valid in thread 0
__device__ float blockMax(float v) {
    __shared__ float sh[NTHREADS / 32];
    __syncthreads();
    int lane = threadIdx.x & 31, w = threadIdx.x >> 5;
    v = warpRedMax(v);
    if (lane == 0) sh[w] = v;
    __syncthreads();
    if (w == 0) {
        v = (lane < NTHREADS / 32) ? sh[lane] : -INFINITY;
        v = warpRedMax(v);
    }
    return v;
}

// ---- transpose C -> g_CT (so the column pass reads coalesced rows) ----
__global__ void transpose_kernel(const float* __restrict__ in) {
    __shared__ float tile[32][33];
    int x = blockIdx.x * 32 + threadIdx.x;
    int y0 = blockIdx.y * 32 + threadIdx.y;
#pragma unroll
    for (int k = 0; k < 32; k += 8)
        tile[threadIdx.y + k][threadIdx.x] = in[(size_t)(y0 + k) * N0 + x];
    __syncthreads();
    int x2 = blockIdx.y * 32 + threadIdx.x;
    int y2 = blockIdx.x * 32 + threadIdx.y;
#pragma unroll
    for (int k = 0; k < 32; k += 8)
        g_CT[(size_t)(y2 + k) * N0 + x2] = tile[threadIdx.x][threadIdx.y + k];
}

// ---- initial state: v = 0, v_pad = 0 -> v_max = 0, w = 0, P = 2048, base = A ----
__global__ void init_kernel() {
    for (int j = threadIdx.x; j < N0; j += blockDim.x) g_w[j] = 0.0f;
    if (threadIdx.x == 0) {
        g_P = 2048.0f;
        g_base = ACONST;
        g_counter = 0u;
    }
}

// One Sinkhorn half-step. phase 0: row update over C (writes g_u / g_upad);
// phase 1: column update over g_CT (writes g_v / g_vpad).
// The last-finishing block computes x_pad, x_max, and the next phase's
// w / P / base in an epilogue (classic fence+atomic-counter pattern).
__global__ void __launch_bounds__(NTHREADS) phase_kernel(const float* __restrict__ C, int phase) {
    const float* __restrict__ M = phase ? g_CT : C;
    float* xout = phase ? g_v : g_u;

    int row = blockIdx.x;
    const float4* m4 = (const float4*)(M + (size_t)row * N0);
    const float4* w4 = (const float4*)g_w;

    float s = 0.0f;
#pragma unroll
    for (int k = 0; k < N0 / 4 / NTHREADS; ++k) {
        int idx = threadIdx.x + k * NTHREADS;
        float4 c = m4[idx];
        float4 w = w4[idx];
        s += ex2(fmaf(-KCONST, c.x, w.x));
        s += ex2(fmaf(-KCONST, c.y, w.y));
        s += ex2(fmaf(-KCONST, c.z, w.z));
        s += ex2(fmaf(-KCONST, c.w, w.w));
    }
    s = blockSum(s);

    __shared__ int amLast;
    if (threadIdx.x == 0) {
        xout[row] = g_base - EPS * logf(s + g_P);
        __threadfence();
        unsigned int t = atomicAdd(&g_counter, 1u);
        amLast = (t == (unsigned)(gridDim.x - 1));
    }
    __syncthreads();
    if (!amLast) return;

    // ---------- epilogue (single block, all prior xout writes visible) ----------
    // x_pad from current-phase weights: LSE over the full padded vector
    float s0 = 0.0f;
    for (int j = threadIdx.x; j < N0; j += NTHREADS) s0 += ex2(g_w[j]);
    s0 = blockSum(s0);

    __shared__ float sh_xpad, sh_xmax;
    if (threadIdx.x == 0) {
        float xp = g_base - EPS * logf(s0 + g_P);
        if (phase) g_vpad = xp; else g_upad = xp;
        sh_xpad = xp;
    }
    __syncthreads();

    // max over the freshly written potential (incl. pad)
    float m = sh_xpad;
    for (int j = threadIdx.x; j < N0; j += NTHREADS) m = fmaxf(m, xout[j]);
    m = blockMax(m);
    if (threadIdx.x == 0) sh_xmax = m;
    __syncthreads();

    float xmax = sh_xmax;
    for (int j = threadIdx.x; j < N0; j += NTHREADS)
        g_w[j] = (xout[j] - xmax) * KCONST;
    if (threadIdx.x == 0) {
        g_P = 2048.0f * ex2((sh_xpad - xmax) * KCONST);
        g_base = ACONST - xmax;
        g_counter = 0u;   // rearm for next launch (replay-safe)
    }
}

// ---- emit 4096x4096 * exp(min(log_pi, 0)) * 4096 ----
__global__ void __launch_bounds__(NTHREADS) final_kernel(const float* __restrict__ C,
                                                         float* __restrict__ out) {
    int i = blockIdx.y;                                  // 0..4095
    int j4 = blockIdx.x * blockDim.x + threadIdx.x;      // float4 index 0..1023

    float u = (i < N0) ? g_u[i] : g_upad;

    float4 v4, c4;
    if (j4 < N0 / 4) {
        v4 = ((const float4*)g_v)[j4];
        if (i < N0)
            c4 = ((const float4*)C)[(size_t)i * (N0 / 4) + j4];
        else
            c4 = make_float4(0.f, 0.f, 0.f, 0.f);
    } else {
        float vp = g_vpad;
        v4 = make_float4(vp, vp, vp, vp);
        c4 = make_float4(0.f, 0.f, 0.f, 0.f);
    }

    float4 o;
    o.x = SCALE * ex2(fminf((u + v4.x - c4.x) * KCONST, 0.0f));
    o.y = SCALE * ex2(fminf((u + v4.y - c4.y) * KCONST, 0.0f));
    o.z = SCALE * ex2(fminf((u + v4.z - c4.z) * KCONST, 0.0f));
    o.w = SCALE * ex2(fminf((u + v4.w - c4.w) * KCONST, 0.0f));

    ((float4*)out)[(size_t)i * (NPAD / 4) + j4] = o;
}

extern "C" void kernel_launch(void* const* d_in, const int* in_sizes, int n_in,
                              void* d_out, int out_size) {
    const float* C = (const float*)d_in[0];
    float* out = (float*)d_out;

    transpose_kernel<<<dim3(N0 / 32, N0 / 32), dim3(32, 8)>>>(C);
    init_kernel<<<1, NTHREADS>>>();

    for (int it = 0; it < 50; ++it) {
        phase_kernel<<<N0, NTHREADS>>>(C, 0);   // row update  -> u
        phase_kernel<<<N0, NTHREADS>>>(C, 1);   // col update  -> v
    }

    final_kernel<<<dim3(NPAD / 4 / NTHREADS, NPAD), NTHREADS>>>(C, out);
}

// round 2
// speedup vs baseline: 1.9484x; 1.9484x over previous
#include <cuda_runtime.h>
#include <math.h>

#define N0 2048
#define NPAD 4096
#define NTHREADS 256

#define EPS 0.05f
// log2(e)/EPS
#define KCONST 28.853900817779268f
// EPS * (-log(4096))
#define ACONST -0.41588830833596715f
// EPS * ln(2)
#define ELN2 0.034657359027997264f
#define SCALE 4096.0f

// ---- device state (no allocations allowed; static globals) ----
__device__ float g_u[N0];
__device__ float g_v[N0];
__device__ float g_upad;
__device__ float g_vpad;
__device__ float g_CT[(size_t)N0 * N0];   // C transposed (16 MB scratch)

__device__ __forceinline__ float ex2(float x) {
    float y;
    asm("ex2.approx.ftz.f32 %0, %1;" : "=f"(y) : "f"(x));
    return y;
}
__device__ __forceinline__ float lg2(float x) {
    float y;
    asm("lg2.approx.ftz.f32 %0, %1;" : "=f"(y) : "f"(x));
    return y;
}

__device__ __forceinline__ float warpRedSum(float v) {
#pragma unroll
    for (int o = 16; o > 0; o >>= 1) v += __shfl_down_sync(0xffffffffu, v, o);
    return v;
}

// ---- transpose C -> g_CT (so the column pass reads coalesced rows) ----
__global__ void transpose_kernel(const float* __restrict__ in) {
    __shared__ float tile[32][33];
    int x = blockIdx.x * 32 + threadIdx.x;
    int y0 = blockIdx.y * 32 + threadIdx.y;
#pragma unroll
    for (int k = 0; k < 32; k += 8)
        tile[threadIdx.y + k][threadIdx.x] = in[(size_t)(y0 + k) * N0 + x];
    __syncthreads();
    int x2 = blockIdx.y * 32 + threadIdx.x;
    int y2 = blockIdx.x * 32 + threadIdx.y;
#pragma unroll
    for (int k = 0; k < 32; k += 8)
        g_CT[(size_t)(y2 + k) * N0 + x2] = tile[threadIdx.x][threadIdx.y + k];
}

// ---- initial state: v = 0, v_pad = 0 ----
__global__ void init_kernel() {
    for (int j = threadIdx.x; j < N0; j += blockDim.x) g_v[j] = 0.0f;
    if (threadIdx.x == 0) g_vpad = 0.0f;
}

// One Sinkhorn half-step, no max-shift (exponents bounded: C in [0,1], eps=0.05
// keeps potentials in ~[-1, 0.5], so exp2 args stay within fp32 range).
//
// phase 0 (row update):  reads v/v_pad, matrix C      -> writes u/u_pad
// phase 1 (col update):  reads u/u_pad, matrix C^T    -> writes v/v_pad
//
// x_out[r] = ACONST - eps*log( sum_j exp2(K*x_in[j] - K*M[r][j]) + P ),
//   P = 2048 * exp2(K*x_pad_in)   (the 2048 zero-padded columns/rows)
// The pad potential itself is the same formula with M-row = 0, computed by
// block 0 / warp 0 in parallel — no serial epilogue, no atomics, no fences.
__global__ void __launch_bounds__(NTHREADS) phase_kernel(const float* __restrict__ C, int phase) {
    const float* __restrict__ M = phase ? g_CT : C;
    const float* __restrict__ xin = phase ? g_u : g_v;
    float* xout = phase ? g_v : g_u;

    __shared__ float kx[N0];

    // stage K * x_in into shared (vectorized)
    {
        const float4* x4 = (const float4*)xin;
        float4* k4 = (float4*)kx;
        for (int j = threadIdx.x; j < N0 / 4; j += NTHREADS) {
            float4 t = x4[j];
            t.x *= KCONST; t.y *= KCONST; t.z *= KCONST; t.w *= KCONST;
            k4[j] = t;
        }
    }
    float xpad_in = phase ? g_upad : g_vpad;
    float P = 2048.0f * ex2(KCONST * xpad_in);
    __syncthreads();

    int warp = threadIdx.x >> 5, lane = threadIdx.x & 31;
    int rowBase = blockIdx.x * 16 + warp * 2;   // two rows per warp

    const float4* r0 = (const float4*)(M + (size_t)rowBase * N0);
    const float4* r1 = (const float4*)(M + (size_t)(rowBase + 1) * N0);
    const float4* kx4 = (const float4*)kx;

    float s0 = 0.0f, s1 = 0.0f;
#pragma unroll
    for (int k = 0; k < 16; ++k) {
        int idx = lane + k * 32;
        float4 w = kx4[idx];
        float4 a = r0[idx];
        float4 b = r1[idx];
        s0 += ex2(fmaf(-KCONST, a.x, w.x));
        s0 += ex2(fmaf(-KCONST, a.y, w.y));
        s0 += ex2(fmaf(-KCONST, a.z, w.z));
        s0 += ex2(fmaf(-KCONST, a.w, w.w));
        s1 += ex2(fmaf(-KCONST, b.x, w.x));
        s1 += ex2(fmaf(-KCONST, b.y, w.y));
        s1 += ex2(fmaf(-KCONST, b.z, w.z));
        s1 += ex2(fmaf(-KCONST, b.w, w.w));
    }
    s0 = warpRedSum(s0);
    s1 = warpRedSum(s1);
    if (lane == 0) {
        xout[rowBase]     = ACONST - ELN2 * lg2(s0 + P);
        xout[rowBase + 1] = ACONST - ELN2 * lg2(s1 + P);
    }

    // pad potential: same update with a zero matrix row (fully parallel)
    if (blockIdx.x == 0 && warp == 0) {
        float sp = 0.0f;
#pragma unroll
        for (int k = 0; k < 16; ++k) {
            float4 w = kx4[lane + k * 32];
            sp += ex2(w.x) + ex2(w.y) + ex2(w.z) + ex2(w.w);
        }
        sp = warpRedSum(sp);
        if (lane == 0) {
            float xp = ACONST - ELN2 * lg2(sp + P);
            if (phase) g_vpad = xp; else g_upad = xp;
        }
    }
}

// ---- emit 4096 * exp(min(log_pi, 0)) over the padded 4096x4096 ----
__global__ void __launch_bounds__(NTHREADS) final_kernel(const float* __restrict__ C,
                                                         float* __restrict__ out) {
    int i = blockIdx.y;                                  // 0..4095
    int j4 = blockIdx.x * blockDim.x + threadIdx.x;      // float4 index 0..1023

    float u = (i < N0) ? g_u[i] : g_upad;

    float4 v4, c4;
    if (j4 < N0 / 4) {
        v4 = ((const float4*)g_v)[j4];
        if (i < N0)
            c4 = ((const float4*)C)[(size_t)i * (N0 / 4) + j4];
        else
            c4 = make_float4(0.f, 0.f, 0.f, 0.f);
    } else {
        float vp = g_vpad;
        v4 = make_float4(vp, vp, vp, vp);
        c4 = make_float4(0.f, 0.f, 0.f, 0.f);
    }

    float4 o;
    o.x = SCALE * ex2(fminf((u + v4.x - c4.x) * KCONST, 0.0f));
    o.y = SCALE * ex2(fminf((u + v4.y - c4.y) * KCONST, 0.0f));
    o.z = SCALE * ex2(fminf((u + v4.z - c4.z) * KCONST, 0.0f));
    o.w = SCALE * ex2(fminf((u + v4.w - c4.w) * KCONST, 0.0f));

    ((float4*)out)[(size_t)i * (NPAD / 4) + j4] = o;
}

extern "C" void kernel_launch(void* const* d_in, const int* in_sizes, int n_in,
                              void* d_out, int out_size) {
    const float* C = (const float*)d_in[0];
    float* out = (float*)d_out;

    transpose_kernel<<<dim3(N0 / 32, N0 / 32), dim3(32, 8)>>>(C);
    init_kernel<<<1, NTHREADS>>>();

    for (int it = 0; it < 50; ++it) {
        phase_kernel<<<N0 / 16, NTHREADS>>>(C, 0);   // row update  -> u, u_pad
        phase_kernel<<<N0 / 16, NTHREADS>>>(C, 1);   // col update  -> v, v_pad
    }

    final_kernel<<<dim3(NPAD / 4 / NTHREADS, NPAD), NTHREADS>>>(C, out);
}